// round 3
// baseline (speedup 1.0000x reference)
#include <cuda_runtime.h>
#include <cuda_bf16.h>

// GAE backward affine suffix scan. Inputs: rewards f32 [B,S], values f32 [B,S],
// dones i32 [B,S], mask i32 [B,S] (prefix mask). Output: [advantages; returns].
//
//   nd    = 1 - done
//   delta = r + GAMMA * values[t+1]*mask[t+1] * nd - v
//   g[t]  = mask[t] ? (delta + GAMMA*LAMBDA*nd * g[t+1]) : 0
//   adv = g ; ret = g + mask*v   (g is exactly 0 where mask==0)
//
// Affine transform per step: T_t(g) = d_t + c_t*g with (c,d) = mask ? (GL*nd, delta) : (0,0).
// Composition (left = earlier in time): a = la*ra, b = lb + la*rb.

#define GAMMA  0.999f
#define LAMBDA 0.95f
#define GL     (GAMMA * LAMBDA)
#define S_LEN  2048
#define TPB    256
#define EPT    8           // TPB*EPT == S_LEN
#define NW     (TPB / 32)  // 8 warps

__global__ __launch_bounds__(TPB, 6)
void gae_kernel(const float* __restrict__ rewards,
                const float* __restrict__ values,
                const int*   __restrict__ dones,
                const int*   __restrict__ mask,
                float* __restrict__ adv_out,
                float* __restrict__ ret_out)
{
    const int tid  = threadIdx.x;
    const unsigned lane = tid & 31u;
    const unsigned warp = tid >> 5;

    const long long base = (long long)blockIdx.x * S_LEN + tid * EPT;

    // Coalesced streaming vector loads (touch-once data -> evict-first).
    const float4* rp = reinterpret_cast<const float4*>(rewards + base);
    const float4* vp = reinterpret_cast<const float4*>(values  + base);
    const int4*   dp = reinterpret_cast<const int4*>(dones + base);
    const int4*   mp = reinterpret_cast<const int4*>(mask  + base);
    float4 r4a = __ldcs(rp);     float4 r4b = __ldcs(rp + 1);
    float4 v4a = __ldcs(vp);     float4 v4b = __ldcs(vp + 1);
    int4   d4a = __ldcs(dp);     int4   d4b = __ldcs(dp + 1);
    int4   m4a = __ldcs(mp);     int4   m4b = __ldcs(mp + 1);

    // Neighbor (t+1) value/mask for last element of the chunk (L1 hit on the
    // next thread's line, or zero past end-of-row).
    float v_next = 0.f, m_next = 0.f;
    if (tid * EPT + EPT < S_LEN) {
        v_next = __ldg(values + base + EPT);
        m_next = (float)__ldg(mask + base + EPT);
    }

    float r[EPT]  = {r4a.x, r4a.y, r4a.z, r4a.w, r4b.x, r4b.y, r4b.z, r4b.w};
    float v[EPT]  = {v4a.x, v4a.y, v4a.z, v4a.w, v4b.x, v4b.y, v4b.z, v4b.w};
    float nd[EPT] = {1.f - (float)d4a.x, 1.f - (float)d4a.y,
                     1.f - (float)d4a.z, 1.f - (float)d4a.w,
                     1.f - (float)d4b.x, 1.f - (float)d4b.y,
                     1.f - (float)d4b.z, 1.f - (float)d4b.w};
    float mk[EPT] = {(float)m4a.x, (float)m4a.y, (float)m4a.z, (float)m4a.w,
                     (float)m4b.x, (float)m4b.y, (float)m4b.z, (float)m4b.w};
    float nv[EPT]    = {v[1], v[2], v[3], v[4], v[5], v[6], v[7], v_next};
    float mnext[EPT] = {mk[1], mk[2], mk[3], mk[4], mk[5], mk[6], mk[7], m_next};

    // Per-element affine transforms (c, d) and folded mk*v; only these three
    // arrays stay live across the scan (24 regs).
    float c[EPT], d[EPT], mkv[EPT];
#pragma unroll
    for (int j = 0; j < EPT; ++j) {
        float nvj   = nv[j] * mnext[j];
        float delta = fmaf(GAMMA * nd[j], nvj, r[j]) - v[j];
        c[j]   = mk[j] * GL * nd[j];
        d[j]   = mk[j] * delta;
        mkv[j] = mk[j] * v[j];
    }

    // Thread-local composition over the 8 steps (reverse time order).
    float A = 1.f, Bc = 0.f;
#pragma unroll
    for (int j = EPT - 1; j >= 0; --j) {
        Bc = fmaf(c[j], Bc, d[j]);
        A  = c[j] * A;
    }

    // Warp-level inclusive suffix scan (Kogge-Stone, shfl_down).
    float a = A, b = Bc;
#pragma unroll
    for (int off = 1; off < 32; off <<= 1) {
        float ra = __shfl_down_sync(0xffffffffu, a, off);
        float rb = __shfl_down_sync(0xffffffffu, b, off);
        if (lane + off < 32) {
            b = fmaf(a, rb, b);
            a = a * ra;
        }
    }
    // Exclusive suffix within warp: E_i = inclusive(i+1); identity at lane 31.
    float ea = __shfl_down_sync(0xffffffffu, a, 1);
    float eb = __shfl_down_sync(0xffffffffu, b, 1);
    if (lane == 31) { ea = 1.f; eb = 0.f; }

    // Cross-warp scan over NW=8 warp aggregates.
    __shared__ float wa[NW];
    __shared__ float wb[NW];
    __shared__ float wcarry[NW];
    if (lane == 0) { wa[warp] = a; wb[warp] = b; }
    __syncthreads();
    if (warp == 0 && lane < NW) {
        float aa = wa[lane], bb = wb[lane];
#pragma unroll
        for (int off = 1; off < NW; off <<= 1) {
            float ra = __shfl_down_sync(0x000000ffu, aa, off);
            float rb = __shfl_down_sync(0x000000ffu, bb, off);
            if (lane + off < NW) {
                bb = fmaf(aa, rb, bb);
                aa = aa * ra;
            }
        }
        float carry = __shfl_down_sync(0x000000ffu, bb, 1);
        if (lane == NW - 1) carry = 0.f;
        wcarry[lane] = carry;
    }
    __syncthreads();

    // Carry entering this thread's chunk from the right, then final pass.
    float g = fmaf(ea, wcarry[warp], eb);

    float adv[EPT], ret[EPT];
#pragma unroll
    for (int j = EPT - 1; j >= 0; --j) {
        g = fmaf(c[j], g, d[j]);   // exactly 0 where mask==0 (c=d=0)
        adv[j] = g;
        ret[j] = g + mkv[j];
    }

    float4* ap = reinterpret_cast<float4*>(adv_out + base);
    float4* tp = reinterpret_cast<float4*>(ret_out + base);
    __stcs(ap,     make_float4(adv[0], adv[1], adv[2], adv[3]));
    __stcs(ap + 1, make_float4(adv[4], adv[5], adv[6], adv[7]));
    __stcs(tp,     make_float4(ret[0], ret[1], ret[2], ret[3]));
    __stcs(tp + 1, make_float4(ret[4], ret[5], ret[6], ret[7]));
}

extern "C" void kernel_launch(void* const* d_in, const int* in_sizes, int n_in,
                              void* d_out, int out_size)
{
    const float* rewards = (const float*)d_in[0];
    const float* values  = (const float*)d_in[1];
    const int*   dones   = (const int*)d_in[2];
    const int*   mask    = (const int*)d_in[3];

    const int total = in_sizes[0];            // B * S
    const int B     = total / S_LEN;

    float* adv_out = (float*)d_out;
    float* ret_out = (float*)d_out + (long long)B * S_LEN;

    gae_kernel<<<B, TPB>>>(rewards, values, dones, mask, adv_out, ret_out);
}

// round 4
// speedup vs baseline: 1.1168x; 1.1168x over previous
#include <cuda_runtime.h>
#include <cuda_bf16.h>

// GAE backward affine suffix scan. Inputs: rewards f32 [B,S], values f32 [B,S],
// dones i32 [B,S], mask i32 [B,S] (prefix mask). Output: [advantages; returns].
//
//   nd    = 1 - done
//   delta = r + GAMMA * values[t+1]*mask[t+1] * nd - v
//   g[t]  = mask[t] ? (delta + GAMMA*LAMBDA*nd * g[t+1]) : 0
//   adv = g ; ret = mask ? g + v : 0
//
// Affine transform per step: T_t(g) = d_t + c_t*g with (c,d) = mask ? (GL*nd, delta) : (0,0).
// Composition (left = earlier in time): a = la*ra, b = lb + la*rb.

#define GAMMA  0.999f
#define LAMBDA 0.95f
#define GL     (GAMMA * LAMBDA)
#define S_LEN  2048
#define TPB    256
#define EPT    8           // TPB*EPT == S_LEN
#define NW     (TPB / 32)  // 8 warps

__global__ __launch_bounds__(TPB)
void gae_kernel(const float* __restrict__ rewards,
                const float* __restrict__ values,
                const int*   __restrict__ dones,
                const int*   __restrict__ mask,
                float* __restrict__ adv_out,
                float* __restrict__ ret_out)
{
    const int tid  = threadIdx.x;
    const unsigned lane = tid & 31u;
    const unsigned warp = tid >> 5;

    const long long base = (long long)blockIdx.x * S_LEN + tid * EPT;

    // Coalesced streaming vector loads (touch-once data -> evict-first).
    const float4* rp = reinterpret_cast<const float4*>(rewards + base);
    const float4* vp = reinterpret_cast<const float4*>(values  + base);
    const int4*   dp = reinterpret_cast<const int4*>(dones + base);
    const int4*   mp = reinterpret_cast<const int4*>(mask  + base);
    float4 r4a = __ldcs(rp);     float4 r4b = __ldcs(rp + 1);
    float4 v4a = __ldcs(vp);     float4 v4b = __ldcs(vp + 1);
    int4   d4a = __ldcs(dp);     int4   d4b = __ldcs(dp + 1);
    int4   m4a = __ldcs(mp);     int4   m4b = __ldcs(mp + 1);

    // Neighbor (t+1) value/mask for the last element of each thread's chunk,
    // via shared-memory exchange (no extra global loads): thread tid needs
    // thread tid+1's first (v, mask); past end-of-row it is 0.
    __shared__ float2 nbr[TPB];
    nbr[tid] = make_float2(v4a.x, (float)m4a.x);
    __syncthreads();
    float v_next = 0.f, m_next = 0.f;
    if (tid + 1 < TPB) {
        float2 n = nbr[tid + 1];
        v_next = n.x;
        m_next = n.y;
    }

    float r[EPT]  = {r4a.x, r4a.y, r4a.z, r4a.w, r4b.x, r4b.y, r4b.z, r4b.w};
    float v[EPT]  = {v4a.x, v4a.y, v4a.z, v4a.w, v4b.x, v4b.y, v4b.z, v4b.w};
    float nd[EPT] = {1.f - (float)d4a.x, 1.f - (float)d4a.y,
                     1.f - (float)d4a.z, 1.f - (float)d4a.w,
                     1.f - (float)d4b.x, 1.f - (float)d4b.y,
                     1.f - (float)d4b.z, 1.f - (float)d4b.w};
    float mk[EPT] = {(float)m4a.x, (float)m4a.y, (float)m4a.z, (float)m4a.w,
                     (float)m4b.x, (float)m4b.y, (float)m4b.z, (float)m4b.w};
    float nv[EPT]    = {v[1], v[2], v[3], v[4], v[5], v[6], v[7], v_next};
    float mnext[EPT] = {mk[1], mk[2], mk[3], mk[4], mk[5], mk[6], mk[7], m_next};

    // Per-element affine transforms (c, d); invalid steps -> (0, 0).
    float c[EPT], d[EPT];
#pragma unroll
    for (int j = 0; j < EPT; ++j) {
        float nvj   = nv[j] * mnext[j];
        float delta = fmaf(GAMMA * nd[j], nvj, r[j]) - v[j];
        c[j] = mk[j] * GL * nd[j];
        d[j] = mk[j] * delta;
    }

    // Thread-local composition over the 8 steps (reverse time order).
    float A = 1.f, Bc = 0.f;
#pragma unroll
    for (int j = EPT - 1; j >= 0; --j) {
        Bc = fmaf(c[j], Bc, d[j]);
        A  = c[j] * A;
    }

    // Warp-level inclusive suffix scan (Kogge-Stone, shfl_down).
    float a = A, b = Bc;
#pragma unroll
    for (int off = 1; off < 32; off <<= 1) {
        float ra = __shfl_down_sync(0xffffffffu, a, off);
        float rb = __shfl_down_sync(0xffffffffu, b, off);
        if (lane + off < 32) {
            b = fmaf(a, rb, b);
            a = a * ra;
        }
    }
    // Exclusive suffix within warp: E_i = inclusive(i+1); identity at lane 31.
    float ea = __shfl_down_sync(0xffffffffu, a, 1);
    float eb = __shfl_down_sync(0xffffffffu, b, 1);
    if (lane == 31) { ea = 1.f; eb = 0.f; }

    // Cross-warp scan over NW=8 warp aggregates.
    __shared__ float wa[NW];
    __shared__ float wb[NW];
    __shared__ float wcarry[NW];
    if (lane == 0) { wa[warp] = a; wb[warp] = b; }
    __syncthreads();
    if (warp == 0 && lane < NW) {
        float aa = wa[lane], bb = wb[lane];
#pragma unroll
        for (int off = 1; off < NW; off <<= 1) {
            float ra = __shfl_down_sync(0x000000ffu, aa, off);
            float rb = __shfl_down_sync(0x000000ffu, bb, off);
            if (lane + off < NW) {
                bb = fmaf(aa, rb, bb);
                aa = aa * ra;
            }
        }
        float carry = __shfl_down_sync(0x000000ffu, bb, 1);
        if (lane == NW - 1) carry = 0.f;
        wcarry[lane] = carry;
    }
    __syncthreads();

    // Carry entering this thread's chunk from the right, then final pass.
    float g = fmaf(ea, wcarry[warp], eb);

    float adv[EPT], ret[EPT];
#pragma unroll
    for (int j = EPT - 1; j >= 0; --j) {
        g = fmaf(c[j], g, d[j]);   // exactly 0 where mask==0 (c=d=0)
        adv[j] = g;
        ret[j] = (mk[j] != 0.f) ? (g + v[j]) : 0.f;
    }

    float4* ap = reinterpret_cast<float4*>(adv_out + base);
    float4* tp = reinterpret_cast<float4*>(ret_out + base);
    __stcs(ap,     make_float4(adv[0], adv[1], adv[2], adv[3]));
    __stcs(ap + 1, make_float4(adv[4], adv[5], adv[6], adv[7]));
    __stcs(tp,     make_float4(ret[0], ret[1], ret[2], ret[3]));
    __stcs(tp + 1, make_float4(ret[4], ret[5], ret[6], ret[7]));
}

extern "C" void kernel_launch(void* const* d_in, const int* in_sizes, int n_in,
                              void* d_out, int out_size)
{
    const float* rewards = (const float*)d_in[0];
    const float* values  = (const float*)d_in[1];
    const int*   dones   = (const int*)d_in[2];
    const int*   mask    = (const int*)d_in[3];

    const int total = in_sizes[0];            // B * S
    const int B     = total / S_LEN;

    float* adv_out = (float*)d_out;
    float* ret_out = (float*)d_out + (long long)B * S_LEN;

    gae_kernel<<<B, TPB>>>(rewards, values, dones, mask, adv_out, ret_out);
}

// round 5
// speedup vs baseline: 1.1549x; 1.0341x over previous
#include <cuda_runtime.h>
#include <cuda_bf16.h>

// GAE backward affine suffix scan. Inputs: rewards f32 [B,S], values f32 [B,S],
// dones i32 [B,S], mask i32 [B,S] (PREFIX mask: 1...1 0...0 per row).
// Output: [advantages; returns], 2*B*S floats.
//
//   L     = #ones in mask row (valid prefix length)
//   nd    = 1 - done
//   delta = r + GAMMA * values[t+1]*[t+1<L] * nd - v
//   g[t]  = [t<L] ? (delta + GAMMA*LAMBDA*nd * g[t+1]) : 0
//   adv = g ; ret = [t<L] ? g + v : 0
//
// Key traffic optimization: the mask row is monotone, so L is found with a
// 3-round warp-parallel boundary search (~65 scattered probes) instead of
// streaming all 2048 words (saves ~64 MiB of the ~400 MiB total traffic).

#define GAMMA  0.999f
#define LAMBDA 0.95f
#define GL     (GAMMA * LAMBDA)
#define S_LEN  2048
#define TPB    256
#define EPT    8           // TPB*EPT == S_LEN
#define NW     (TPB / 32)  // 8 warps

__global__ __launch_bounds__(TPB)
void gae_kernel(const float* __restrict__ rewards,
                const float* __restrict__ values,
                const int*   __restrict__ dones,
                const int*   __restrict__ mask,
                float* __restrict__ adv_out,
                float* __restrict__ ret_out)
{
    const int tid  = threadIdx.x;
    const unsigned lane = tid & 31u;
    const unsigned warp = tid >> 5;

    const long long rowbase = (long long)blockIdx.x * S_LEN;
    const long long base    = rowbase + tid * EPT;

    // Coalesced streaming vector loads (touch-once -> evict-first). Issue
    // these first so the boundary search below overlaps with them.
    const float4* rp = reinterpret_cast<const float4*>(rewards + base);
    const float4* vp = reinterpret_cast<const float4*>(values  + base);
    const int4*   dp = reinterpret_cast<const int4*>(dones + base);
    float4 r4a = __ldcs(rp);     float4 r4b = __ldcs(rp + 1);
    float4 v4a = __ldcs(vp);     float4 v4b = __ldcs(vp + 1);
    int4   d4a = __ldcs(dp);     int4   d4b = __ldcs(dp + 1);

    // Warp 0: find L = prefix length of the mask row (monotone 1s then 0s).
    __shared__ int L_sh;
    if (warp == 0) {
        const int* mrow = mask + rowbase;
        // Round 1: 32 probes at stride 64.
        int p1 = __ldg(mrow + lane * 64);
        unsigned b1 = __ballot_sync(0xffffffffu, p1 != 0);
        int L;
        if (b1 == 0u) {
            L = 0;
        } else {
            int k = __popc(b1);               // ones at lanes 0..k-1
            int base64 = (k - 1) * 64;        // L in (base64, base64+64]
            // Round 2: 32 probes at stride 2 within the window.
            int p2 = __ldg(mrow + base64 + lane * 2);
            int k2 = __popc(__ballot_sync(0xffffffffu, p2 != 0));
            // L in (base64 + 2*(k2-1), base64 + 2*k2]
            int cand = base64 + 2 * k2;       // either cand or cand-1
            // Round 3: single probe at cand-1.
            int p3 = __ldg(mrow + (cand - 1));
            L = p3 ? cand : cand - 1;
        }
        if (lane == 0) L_sh = L;
    }

    // Neighbor (t+1) value for the last element of each thread's chunk via
    // shared-memory exchange.
    __shared__ float nbr[TPB];
    nbr[tid] = v4a.x;
    __syncthreads();
    const int L = L_sh;
    float v_next = (tid + 1 < TPB) ? nbr[tid + 1] : 0.f;

    float r[EPT]  = {r4a.x, r4a.y, r4a.z, r4a.w, r4b.x, r4b.y, r4b.z, r4b.w};
    float v[EPT]  = {v4a.x, v4a.y, v4a.z, v4a.w, v4b.x, v4b.y, v4b.z, v4b.w};
    float nd[EPT] = {1.f - (float)d4a.x, 1.f - (float)d4a.y,
                     1.f - (float)d4a.z, 1.f - (float)d4a.w,
                     1.f - (float)d4b.x, 1.f - (float)d4b.y,
                     1.f - (float)d4b.z, 1.f - (float)d4b.w};
    float nv[EPT] = {v[1], v[2], v[3], v[4], v[5], v[6], v[7], v_next};

    const int t0 = tid * EPT;

    // Per-element affine transforms (c, d); invalid steps -> (0, 0).
    float c[EPT], d[EPT], mk[EPT];
#pragma unroll
    for (int j = 0; j < EPT; ++j) {
        float m  = (t0 + j     < L) ? 1.f : 0.f;
        float mn = (t0 + j + 1 < L) ? 1.f : 0.f;
        float nvj   = nv[j] * mn;                 // zero past last valid step
        float delta = fmaf(GAMMA * nd[j], nvj, r[j]) - v[j];
        c[j]  = m * GL * nd[j];
        d[j]  = m * delta;
        mk[j] = m;
    }

    // Thread-local composition over the 8 steps (reverse time order).
    float A = 1.f, Bc = 0.f;
#pragma unroll
    for (int j = EPT - 1; j >= 0; --j) {
        Bc = fmaf(c[j], Bc, d[j]);
        A  = c[j] * A;
    }

    // Warp-level inclusive suffix scan (Kogge-Stone, shfl_down).
    float a = A, b = Bc;
#pragma unroll
    for (int off = 1; off < 32; off <<= 1) {
        float ra = __shfl_down_sync(0xffffffffu, a, off);
        float rb = __shfl_down_sync(0xffffffffu, b, off);
        if (lane + off < 32) {
            b = fmaf(a, rb, b);
            a = a * ra;
        }
    }
    // Exclusive suffix within warp: E_i = inclusive(i+1); identity at lane 31.
    float ea = __shfl_down_sync(0xffffffffu, a, 1);
    float eb = __shfl_down_sync(0xffffffffu, b, 1);
    if (lane == 31) { ea = 1.f; eb = 0.f; }

    // Cross-warp scan over NW=8 warp aggregates.
    __shared__ float wa[NW];
    __shared__ float wb[NW];
    __shared__ float wcarry[NW];
    if (lane == 0) { wa[warp] = a; wb[warp] = b; }
    __syncthreads();
    if (warp == 0 && lane < NW) {
        float aa = wa[lane], bb = wb[lane];
#pragma unroll
        for (int off = 1; off < NW; off <<= 1) {
            float ra = __shfl_down_sync(0x000000ffu, aa, off);
            float rb = __shfl_down_sync(0x000000ffu, bb, off);
            if (lane + off < NW) {
                bb = fmaf(aa, rb, bb);
                aa = aa * ra;
            }
        }
        float carry = __shfl_down_sync(0x000000ffu, bb, 1);
        if (lane == NW - 1) carry = 0.f;
        wcarry[lane] = carry;
    }
    __syncthreads();

    // Carry entering this thread's chunk from the right, then final pass.
    float g = fmaf(ea, wcarry[warp], eb);

    float adv[EPT], ret[EPT];
#pragma unroll
    for (int j = EPT - 1; j >= 0; --j) {
        g = fmaf(c[j], g, d[j]);   // exactly 0 where invalid (c=d=0)
        adv[j] = g;
        ret[j] = (mk[j] != 0.f) ? (g + v[j]) : 0.f;
    }

    float4* ap = reinterpret_cast<float4*>(adv_out + base);
    float4* tp = reinterpret_cast<float4*>(ret_out + base);
    __stcs(ap,     make_float4(adv[0], adv[1], adv[2], adv[3]));
    __stcs(ap + 1, make_float4(adv[4], adv[5], adv[6], adv[7]));
    __stcs(tp,     make_float4(ret[0], ret[1], ret[2], ret[3]));
    __stcs(tp + 1, make_float4(ret[4], ret[5], ret[6], ret[7]));
}

extern "C" void kernel_launch(void* const* d_in, const int* in_sizes, int n_in,
                              void* d_out, int out_size)
{
    const float* rewards = (const float*)d_in[0];
    const float* values  = (const float*)d_in[1];
    const int*   dones   = (const int*)d_in[2];
    const int*   mask    = (const int*)d_in[3];

    const int total = in_sizes[0];            // B * S
    const int B     = total / S_LEN;

    float* adv_out = (float*)d_out;
    float* ret_out = (float*)d_out + (long long)B * S_LEN;

    gae_kernel<<<B, TPB>>>(rewards, values, dones, mask, adv_out, ret_out);
}

// round 6
// speedup vs baseline: 1.1679x; 1.0113x over previous
#include <cuda_runtime.h>
#include <cuda_bf16.h>

// GAE backward affine suffix scan. Inputs: rewards f32 [B,S], values f32 [B,S],
// dones i32 [B,S], mask i32 [B,S] (PREFIX mask: 1...1 0...0 per row).
// Output: [advantages; returns], 2*B*S floats.
//
// Two kernels:
//  1) len_kernel: one warp per row finds L = prefix length via a 2-round
//     warp-parallel boundary search (96 scattered probes vs 2048 streamed
//     words; saves ~64 MiB of HBM traffic). Chains overlap across 8192 warps.
//  2) gae_kernel: streaming affine suffix scan; mask replaced by t < L.

#define GAMMA  0.999f
#define LAMBDA 0.95f
#define GL     (GAMMA * LAMBDA)
#define S_LEN  2048
#define TPB    256
#define EPT    8           // TPB*EPT == S_LEN
#define NW     (TPB / 32)  // 8 warps
#define MAX_B  8192

__device__ int g_L[MAX_B];

__global__ __launch_bounds__(256)
void len_kernel(const int* __restrict__ mask, int B)
{
    const int gw   = (blockIdx.x * 256 + threadIdx.x) >> 5;   // warp id = row
    const int lane = threadIdx.x & 31;
    if (gw >= B) return;

    const int* mrow = mask + (long long)gw * S_LEN;

    // Round 1: 32 probes at stride 64. mask[64*lane]=1 iff 64*lane < L.
    int p1 = __ldg(mrow + lane * 64);
    unsigned b1 = __ballot_sync(0xffffffffu, p1 != 0);

    int L = 0;
    if (b1 != 0u) {
        int k  = __popc(b1);          // ones at lanes 0..k-1 -> L in (64(k-1), 64k]
        int w0 = (k - 1) * 64;
        // Round 2: 64 probes (2 independent loads per lane) in the window.
        int q0 = __ldg(mrow + w0 + 2 * lane);
        int q1 = __ldg(mrow + w0 + 2 * lane + 1);
        unsigned c0 = __ballot_sync(0xffffffffu, q0 != 0);
        unsigned c1 = __ballot_sync(0xffffffffu, q1 != 0);
        L = w0 + __popc(c0) + __popc(c1);   // ones in window = L - w0
    }
    if (lane == 0) g_L[gw] = L;
}

__global__ __launch_bounds__(TPB)
void gae_kernel(const float* __restrict__ rewards,
                const float* __restrict__ values,
                const int*   __restrict__ dones,
                float* __restrict__ adv_out,
                float* __restrict__ ret_out)
{
    const int tid  = threadIdx.x;
    const unsigned lane = tid & 31u;
    const unsigned warp = tid >> 5;

    const long long base = (long long)blockIdx.x * S_LEN + tid * EPT;

    // Broadcast scalar: valid prefix length for this row.
    const int L = __ldg(&g_L[blockIdx.x]);

    // Coalesced streaming vector loads (touch-once -> evict-first).
    const float4* rp = reinterpret_cast<const float4*>(rewards + base);
    const float4* vp = reinterpret_cast<const float4*>(values  + base);
    const int4*   dp = reinterpret_cast<const int4*>(dones + base);
    float4 r4a = __ldcs(rp);     float4 r4b = __ldcs(rp + 1);
    float4 v4a = __ldcs(vp);     float4 v4b = __ldcs(vp + 1);
    int4   d4a = __ldcs(dp);     int4   d4b = __ldcs(dp + 1);

    // Neighbor (t+1) value for the last element of each thread's chunk via
    // shared-memory exchange.
    __shared__ float nbr[TPB];
    nbr[tid] = v4a.x;
    __syncthreads();
    float v_next = (tid + 1 < TPB) ? nbr[tid + 1] : 0.f;

    float r[EPT]  = {r4a.x, r4a.y, r4a.z, r4a.w, r4b.x, r4b.y, r4b.z, r4b.w};
    float v[EPT]  = {v4a.x, v4a.y, v4a.z, v4a.w, v4b.x, v4b.y, v4b.z, v4b.w};
    float nd[EPT] = {1.f - (float)d4a.x, 1.f - (float)d4a.y,
                     1.f - (float)d4a.z, 1.f - (float)d4a.w,
                     1.f - (float)d4b.x, 1.f - (float)d4b.y,
                     1.f - (float)d4b.z, 1.f - (float)d4b.w};
    float nv[EPT] = {v[1], v[2], v[3], v[4], v[5], v[6], v[7], v_next};

    const int t0 = tid * EPT;

    // Per-element affine transforms (c, d); invalid steps -> (0, 0).
    float c[EPT], d[EPT], mk[EPT];
#pragma unroll
    for (int j = 0; j < EPT; ++j) {
        float m  = (t0 + j     < L) ? 1.f : 0.f;
        float mn = (t0 + j + 1 < L) ? 1.f : 0.f;
        float nvj   = nv[j] * mn;                 // zero past last valid step
        float delta = fmaf(GAMMA * nd[j], nvj, r[j]) - v[j];
        c[j]  = m * GL * nd[j];
        d[j]  = m * delta;
        mk[j] = m;
    }

    // Thread-local composition over the 8 steps (reverse time order).
    float A = 1.f, Bc = 0.f;
#pragma unroll
    for (int j = EPT - 1; j >= 0; --j) {
        Bc = fmaf(c[j], Bc, d[j]);
        A  = c[j] * A;
    }

    // Warp-level inclusive suffix scan (Kogge-Stone, shfl_down).
    float a = A, b = Bc;
#pragma unroll
    for (int off = 1; off < 32; off <<= 1) {
        float ra = __shfl_down_sync(0xffffffffu, a, off);
        float rb = __shfl_down_sync(0xffffffffu, b, off);
        if (lane + off < 32) {
            b = fmaf(a, rb, b);
            a = a * ra;
        }
    }
    // Exclusive suffix within warp: E_i = inclusive(i+1); identity at lane 31.
    float ea = __shfl_down_sync(0xffffffffu, a, 1);
    float eb = __shfl_down_sync(0xffffffffu, b, 1);
    if (lane == 31) { ea = 1.f; eb = 0.f; }

    // Cross-warp scan over NW=8 warp aggregates.
    __shared__ float wa[NW];
    __shared__ float wb[NW];
    __shared__ float wcarry[NW];
    if (lane == 0) { wa[warp] = a; wb[warp] = b; }
    __syncthreads();
    if (warp == 0 && lane < NW) {
        float aa = wa[lane], bb = wb[lane];
#pragma unroll
        for (int off = 1; off < NW; off <<= 1) {
            float ra = __shfl_down_sync(0x000000ffu, aa, off);
            float rb = __shfl_down_sync(0x000000ffu, bb, off);
            if (lane + off < NW) {
                bb = fmaf(aa, rb, bb);
                aa = aa * ra;
            }
        }
        float carry = __shfl_down_sync(0x000000ffu, bb, 1);
        if (lane == NW - 1) carry = 0.f;
        wcarry[lane] = carry;
    }
    __syncthreads();

    // Carry entering this thread's chunk from the right, then final pass.
    float g = fmaf(ea, wcarry[warp], eb);

    float adv[EPT], ret[EPT];
#pragma unroll
    for (int j = EPT - 1; j >= 0; --j) {
        g = fmaf(c[j], g, d[j]);   // exactly 0 where invalid (c=d=0)
        adv[j] = g;
        ret[j] = (mk[j] != 0.f) ? (g + v[j]) : 0.f;
    }

    float4* ap = reinterpret_cast<float4*>(adv_out + base);
    float4* tp = reinterpret_cast<float4*>(ret_out + base);
    __stcs(ap,     make_float4(adv[0], adv[1], adv[2], adv[3]));
    __stcs(ap + 1, make_float4(adv[4], adv[5], adv[6], adv[7]));
    __stcs(tp,     make_float4(ret[0], ret[1], ret[2], ret[3]));
    __stcs(tp + 1, make_float4(ret[4], ret[5], ret[6], ret[7]));
}

extern "C" void kernel_launch(void* const* d_in, const int* in_sizes, int n_in,
                              void* d_out, int out_size)
{
    const float* rewards = (const float*)d_in[0];
    const float* values  = (const float*)d_in[1];
    const int*   dones   = (const int*)d_in[2];
    const int*   mask    = (const int*)d_in[3];

    const int total = in_sizes[0];            // B * S
    const int B     = total / S_LEN;

    float* adv_out = (float*)d_out;
    float* ret_out = (float*)d_out + (long long)B * S_LEN;

    // Kernel 1: per-row prefix lengths (one warp per row).
    const int lb = 256;
    const int lg = (B * 32 + lb - 1) / lb;
    len_kernel<<<lg, lb>>>(mask, B);

    // Kernel 2: streaming GAE scan.
    gae_kernel<<<B, TPB>>>(rewards, values, dones, adv_out, ret_out);
}